// round 17
// baseline (speedup 1.0000x reference)
#include <cuda_runtime.h>
#include <cuda_fp16.h>
#include <mma.h>
using namespace nvcuda;

#define N_NODES 50000
#define N_EDGES 800000
#define D 64
#define CAP 64        // max in-degree bucket; Poisson(16) tail @64 ~ 1e-20
#define N_TILES 3125  // 50000 / 16  (exact)

// ---------------------------------------------------------------------------
// Device scratch
// ---------------------------------------------------------------------------
__device__ float g_deg[N_NODES];
__device__ float g_dinv[N_NODES];
__device__ int   g_cnt[N_NODES];                        // in-degree, also fill cursor
__device__ __align__(16) unsigned g_csr[N_NODES * CAP]; // packed: src(lo16) | half(w)(hi16)
__device__ __align__(16) __half g_hA[N_NODES * D];      // h ping
__device__ __align__(16) __half g_hB[N_NODES * D];      // h pong
__device__ __align__(16) __half g_a16[N_NODES * D];     // dinv-scaled fp16 layer-0 input

// ---------------------------------------------------------------------------
__global__ void init_kernel() {
    int i = blockIdx.x * blockDim.x + threadIdx.x;
    if (i < N_NODES) { g_deg[i] = 1.0f; g_cnt[i] = 0; }
}

__global__ void build_kernel(const int* __restrict__ ei,
                             const float* __restrict__ ew) {
    int e = blockIdx.x * blockDim.x + threadIdx.x;
    if (e >= N_EDGES) return;
    int s = __ldg(ei + e);
    int d = __ldg(ei + N_EDGES + e);
    float w = __ldg(ew + e);
    atomicAdd(&g_deg[d], w);
    int pos = atomicAdd(&g_cnt[d], 1);
    if (pos < CAP) {
        unsigned hw = (unsigned)__half_as_ushort(__float2half_rn(w));
        g_csr[d * CAP + pos] = (unsigned)s | (hw << 16);
    }
}

__global__ void dinv_kernel() {
    int i = blockIdx.x * blockDim.x + threadIdx.x;
    if (i < N_NODES) g_dinv[i] = rsqrtf(g_deg[i]);  // deg >= 1 always
}

// ---------------------------------------------------------------------------
// Convert fp32 x -> fp16 g_a16, scaled by dinv[row]. 8 elems/thread.
// ---------------------------------------------------------------------------
__global__ void x16_kernel(const float* __restrict__ x) {
    int idx = blockIdx.x * blockDim.x + threadIdx.x;   // over N*D/8
    if (idx >= N_NODES * D / 8) return;
    int row = idx >> 3;
    float dv = g_dinv[row];
    const float4* xp = (const float4*)x + 2 * idx;
    float4 v0 = xp[0];
    float4 v1 = xp[1];
    union { __half2 h2[4]; uint4 u4; } pk;
    pk.h2[0] = __floats2half2_rn(dv * v0.x, dv * v0.y);
    pk.h2[1] = __floats2half2_rn(dv * v0.z, dv * v0.w);
    pk.h2[2] = __floats2half2_rn(dv * v1.x, dv * v1.y);
    pk.h2[3] = __floats2half2_rn(dv * v1.z, dv * v1.w);
    ((uint4*)g_a16)[idx] = pk.u4;
}

// ---------------------------------------------------------------------------
// Warp-level aggregate for node n: y = relu( dinv[n]*(sum + self) + b )
// lane l owns columns (2l, 2l+1). ILP-4 (R16-proven). Returns (y0, y1).
// ---------------------------------------------------------------------------
__device__ __forceinline__ float2 warp_aggregate(const __half* __restrict__ hin,
                                                 int n, int lane,
                                                 const float* __restrict__ b) {
    const __half2* hn = (const __half2*)(hin + (size_t)n * D);
    float2 hv = __half22float2(hn[lane]);
    float a0 = hv.x, a1 = hv.y;          // self term h~[n]
    float c0 = 0.0f, c1 = 0.0f;
    float e0 = 0.0f, e1 = 0.0f;
    float f0 = 0.0f, f1 = 0.0f;

    int cnt = min(g_cnt[n], CAP);
    const uint4* csr4 = (const uint4*)(g_csr + (size_t)n * CAP);

    int j = 0;
    for (; j + 4 <= cnt; j += 4) {
        uint4 q = csr4[j >> 2];
        const __half2* h0 = (const __half2*)(hin + (size_t)(q.x & 0xFFFFu) * D);
        const __half2* h1 = (const __half2*)(hin + (size_t)(q.y & 0xFFFFu) * D);
        const __half2* h2 = (const __half2*)(hin + (size_t)(q.z & 0xFFFFu) * D);
        const __half2* h3 = (const __half2*)(hin + (size_t)(q.w & 0xFFFFu) * D);
        float2 v0 = __half22float2(h0[lane]);
        float2 v1 = __half22float2(h1[lane]);
        float2 v2 = __half22float2(h2[lane]);
        float2 v3 = __half22float2(h3[lane]);
        float n0 = __half2float(__ushort_as_half((unsigned short)(q.x >> 16)));
        float n1 = __half2float(__ushort_as_half((unsigned short)(q.y >> 16)));
        float n2 = __half2float(__ushort_as_half((unsigned short)(q.z >> 16)));
        float n3 = __half2float(__ushort_as_half((unsigned short)(q.w >> 16)));
        a0 = fmaf(n0, v0.x, a0);  a1 = fmaf(n0, v0.y, a1);
        c0 = fmaf(n1, v1.x, c0);  c1 = fmaf(n1, v1.y, c1);
        e0 = fmaf(n2, v2.x, e0);  e1 = fmaf(n2, v2.y, e1);
        f0 = fmaf(n3, v3.x, f0);  f1 = fmaf(n3, v3.y, f1);
    }
    for (; j < cnt; j++) {
        unsigned q = g_csr[(size_t)n * CAP + j];
        const __half2* hs = (const __half2*)(hin + (size_t)(q & 0xFFFFu) * D);
        float2 v = __half22float2(hs[lane]);
        float nrm = __half2float(__ushort_as_half((unsigned short)(q >> 16)));
        a0 = fmaf(nrm, v.x, a0);
        a1 = fmaf(nrm, v.y, a1);
    }
    a0 += c0 + e0 + f0;
    a1 += c1 + e1 + f1;

    float dv = g_dinv[n];
    float2 bb = ((const float2*)b)[lane];
    a0 = fmaxf(fmaf(dv, a0, bb.x), 0.0f);
    a1 = fmaxf(fmaf(dv, a1, bb.y), 0.0f);
    return make_float2(a0, a1);
}

// ---------------------------------------------------------------------------
// Standalone wmma GEMM (layer 0): hout = fp16( a_in @ W ), a_in pre-scaled.
// 4 warps/block, one 16-row tile/warp; per-n-tile 16x16 smem epilogue.
// ---------------------------------------------------------------------------
__global__ void gemm_wmma_kernel(const __half* __restrict__ a_in,
                                 __half* __restrict__ hout,
                                 const float* __restrict__ W) {
    __shared__ __half Wh[D * D];
    __shared__ float  Cs[4][16 * 16];

    int tid = threadIdx.x;
    for (int i = tid; i < D * D; i += 128) Wh[i] = __float2half_rn(W[i]);
    __syncthreads();

    int warp = tid >> 5;
    int lane = tid & 31;
    int tile = blockIdx.x * 4 + warp;
    if (tile >= N_TILES) return;

    const __half* a_ptr = a_in + (size_t)tile * 16 * D;

    wmma::fragment<wmma::matrix_a, 16, 16, 16, __half, wmma::row_major> a[4];
#pragma unroll
    for (int k = 0; k < 4; k++)
        wmma::load_matrix_sync(a[k], a_ptr + k * 16, D);

    int row = lane & 15;
    int grp = lane >> 4;

#pragma unroll
    for (int n = 0; n < 4; n++) {
        wmma::fragment<wmma::accumulator, 16, 16, 16, float> c;
        wmma::fill_fragment(c, 0.0f);
#pragma unroll
        for (int k = 0; k < 4; k++) {
            wmma::fragment<wmma::matrix_b, 16, 16, 16, __half, wmma::row_major> b;
            wmma::load_matrix_sync(b, Wh + k * 16 * D + n * 16, D);
            wmma::mma_sync(c, a[k], b, c);
        }
        wmma::store_matrix_sync(&Cs[warp][0], c, 16, wmma::mem_row_major);
        __syncwarp();
        const float* cs = &Cs[warp][row * 16 + grp * 8];
        union { __half2 h2[4]; uint4 u4; } pk;
        pk.h2[0] = __floats2half2_rn(cs[0], cs[1]);
        pk.h2[1] = __floats2half2_rn(cs[2], cs[3]);
        pk.h2[2] = __floats2half2_rn(cs[4], cs[5]);
        pk.h2[3] = __floats2half2_rn(cs[6], cs[7]);
        *(uint4*)(hout + (size_t)(tile * 16 + row) * D + n * 16 + grp * 8) = pk.u4;
        __syncwarp();
    }
}

// ---------------------------------------------------------------------------
// Fused: aggregate 16 nodes (16 warps, 1 node/warp) -> smem fp16 rows ->
// wmma GEMM (warps 0-3, one n-tile each) -> hout. 512 threads/block.
// W conversion overlaps the aggregate (sync only after As writes).
// ---------------------------------------------------------------------------
__global__ __launch_bounds__(512)
void fused_agg_gemm_kernel(const __half* __restrict__ hin,
                           __half* __restrict__ hout,
                           const float* __restrict__ b,
                           const float* __restrict__ W) {
    __shared__ __half Wh[D * D];
    __shared__ __half As[16 * D];
    __shared__ float  Cs[4][16 * 16];

    int tid  = threadIdx.x;
    int warp = tid >> 5;
    int lane = tid & 31;

    for (int i = tid; i < D * D; i += 512) Wh[i] = __float2half_rn(W[i]);

    int n = blockIdx.x * 16 + warp;      // exact: 3125*16 = 50000
    float2 y = warp_aggregate(hin, n, lane, b);
    float dv = g_dinv[n];
    ((__half2*)(As + warp * D))[lane] = __floats2half2_rn(y.x * dv, y.y * dv);
    __syncthreads();

    if (warp < 4) {
        wmma::fragment<wmma::matrix_a, 16, 16, 16, __half, wmma::row_major> a[4];
#pragma unroll
        for (int k = 0; k < 4; k++)
            wmma::load_matrix_sync(a[k], As + k * 16, D);

        int row = lane & 15;
        int grp = lane >> 4;
        int nt  = warp;                  // n-tile

        wmma::fragment<wmma::accumulator, 16, 16, 16, float> c;
        wmma::fill_fragment(c, 0.0f);
#pragma unroll
        for (int k = 0; k < 4; k++) {
            wmma::fragment<wmma::matrix_b, 16, 16, 16, __half, wmma::row_major> bf;
            wmma::load_matrix_sync(bf, Wh + k * 16 * D + nt * 16, D);
            wmma::mma_sync(c, a[k], bf, c);
        }
        wmma::store_matrix_sync(&Cs[warp][0], c, 16, wmma::mem_row_major);
        __syncwarp();
        const float* cs = &Cs[warp][row * 16 + grp * 8];
        union { __half2 h2[4]; uint4 u4; } pk;
        pk.h2[0] = __floats2half2_rn(cs[0], cs[1]);
        pk.h2[1] = __floats2half2_rn(cs[2], cs[3]);
        pk.h2[2] = __floats2half2_rn(cs[4], cs[5]);
        pk.h2[3] = __floats2half2_rn(cs[6], cs[7]);
        *(uint4*)(hout + (size_t)(blockIdx.x * 16 + row) * D + nt * 16 + grp * 8) = pk.u4;
    }
}

// ---------------------------------------------------------------------------
// Final aggregate: fp32 out
// ---------------------------------------------------------------------------
__global__ void agg_last_kernel(const __half* __restrict__ hin,
                                const float* __restrict__ b,
                                float* __restrict__ out) {
    int warp = (blockIdx.x * blockDim.x + threadIdx.x) >> 5;
    int lane = threadIdx.x & 31;
    if (warp >= N_NODES) return;
    float2 y = warp_aggregate(hin, warp, lane, b);
    float2* op = (float2*)(out + (size_t)warp * D);
    op[lane] = make_float2(y.x, y.y);
}

// ---------------------------------------------------------------------------
extern "C" void kernel_launch(void* const* d_in, const int* in_sizes, int n_in,
                              void* d_out, int out_size) {
    const float* x  = (const float*)d_in[0];
    const int*   ei = (const int*)d_in[1];
    const float* ew = (const float*)d_in[2];
    const float* W0 = (const float*)d_in[3];
    const float* b0 = (const float*)d_in[4];
    const float* W1 = (const float*)d_in[5];
    const float* b1 = (const float*)d_in[6];
    const float* W2 = (const float*)d_in[7];
    const float* b2 = (const float*)d_in[8];
    float* out = (float*)d_out;

    // resolve device-symbol addresses is implicit (g_* referenced in kernels)
    __half* hA = nullptr; __half* hB = nullptr; __half* a16 = nullptr;
    cudaGetSymbolAddress((void**)&hA,  g_hA);
    cudaGetSymbolAddress((void**)&hB,  g_hB);
    cudaGetSymbolAddress((void**)&a16, g_a16);

    const int TB = 256;
    const int gN = (N_NODES + TB - 1) / TB;            // 196
    const int gE = (N_EDGES + TB - 1) / TB;            // 3125
    const int gW = (N_NODES * 32 + TB - 1) / TB;       // 6250 (warp/node)
    const int gX = (N_NODES * D / 8 + TB - 1) / TB;    // 1563
    const int gG = (N_TILES + 3) / 4;                  // 782

    // ---- bucketed CSR build ----
    init_kernel<<<gN, TB>>>();
    build_kernel<<<gE, TB>>>(ei, ew);
    dinv_kernel<<<gN, TB>>>();
    x16_kernel<<<gX, TB>>>(x);

    // ---- layer 0 GEMM ----
    gemm_wmma_kernel<<<gG, 128>>>(a16, hA, W0);

    // ---- fused agg(L0) + GEMM(L1) ----
    fused_agg_gemm_kernel<<<N_TILES, 512>>>(hA, hB, b0, W1);

    // ---- fused agg(L1) + GEMM(L2) ----
    fused_agg_gemm_kernel<<<N_TILES, 512>>>(hB, hA, b1, W2);

    // ---- final aggregate ----
    agg_last_kernel<<<gW, TB>>>(hA, b2, out);
}